// round 6
// baseline (speedup 1.0000x reference)
#include <cuda_runtime.h>
#include <cuda_fp16.h>
#include <cstdint>

#define MROWS 8192   // B*N tokens
#define KPROT 8192   // prototypes
#define DDIM  768
#define INV_TT (1.0f/0.07f)
#define INV_ST 10.0f
#define SK_EPS 1e-8f
#define SHIFT  9.0f

// ---------------- scratch (static device globals; no allocation) -------------
static __device__ __align__(16) __half g_Lt[(size_t)MROWS * KPROT];
static __device__ __align__(16) __half g_Ls[(size_t)MROWS * KPROT];
static __device__ __align__(16) __half g_Et[(size_t)MROWS * KPROT];  // exp(Lt/tt - shift)
static __device__ __align__(16) int8_t g_ti8[MROWS * DDIM];   // quantized normalized teacher
static __device__ __align__(16) int8_t g_si8[MROWS * DDIM];   // quantized normalized student
static __device__ __align__(16) int8_t g_wi8[KPROT * DDIM];   // quantized W direction (shared)
static __device__ float  g_scT[MROWS];    // dequant scale (normalized teacher)
static __device__ float  g_scS[MROWS];    // dequant scale (normalized student)
static __device__ float  g_scWr[KPROT];   // dequant scale -> raw W
static __device__ float  g_scWn[KPROT];   // dequant scale -> normalized W
static __device__ float  g_S[KPROT];
static __device__ float  g_r[KPROT];
static __device__ float  g_c[MROWS];
static __device__ float  g_msk[MROWS];
static __device__ int    g_maxd[KPROT];
static __device__ float  g_acc[4];
static __device__ int    g_maskmode;

// ---------------- reductions ---------------------------------------------------
__device__ __forceinline__ float warpSum(float v) {
#pragma unroll
    for (int o = 16; o > 0; o >>= 1) v += __shfl_down_sync(0xffffffffu, v, o);
    return v;
}
__device__ float blockSum(float v) {
    __shared__ float sb[32];
    int lane = threadIdx.x & 31, w = threadIdx.x >> 5;
    v = warpSum(v);
    __syncthreads();
    if (lane == 0) sb[w] = v;
    __syncthreads();
    int nw = (blockDim.x + 31) >> 5;
    v = (threadIdx.x < nw) ? sb[threadIdx.x] : 0.f;
    if (w == 0) v = warpSum(v);
    return v;
}

// ---------------- mask handling -------------------------------------------------
__global__ void detect_mask_kernel(const unsigned char* __restrict__ p) {
    __shared__ int c0, c1, c23;
    if (threadIdx.x == 0) { c0 = 0; c1 = 0; c23 = 0; }
    __syncthreads();
    int l0 = 0, l1 = 0, l23 = 0;
    for (int i = threadIdx.x; i < MROWS; i += blockDim.x) {
        unsigned char b = p[i];
        if (b) { int r = i & 3; if (r == 0) l0++; else if (r == 1) l1++; else l23++; }
    }
    atomicAdd(&c0, l0); atomicAdd(&c1, l1); atomicAdd(&c23, l23);
    __syncthreads();
    if (threadIdx.x == 0) {
        int mode;
        if (c1 == 0 && c23 == 0) mode = (c0 > 0) ? 1 : 0;
        else if (c1 == 0)        mode = 2;
        else                     mode = 0;
        g_maskmode = mode;
    }
}
__global__ void build_mask_kernel(const void* __restrict__ p) {
    int m = blockIdx.x * blockDim.x + threadIdx.x;
    if (m >= MROWS) return;
    int mode = g_maskmode;
    float v;
    if (mode == 1)      v = (((const int*)p)[m] != 0) ? 1.f : 0.f;
    else if (mode == 2) v = (((const float*)p)[m] != 0.f) ? 1.f : 0.f;
    else                v = (((const unsigned char*)p)[m] != 0) ? 1.f : 0.f;
    g_msk[m] = v;
}

__global__ void init_kernel() {
    int i = blockIdx.x * blockDim.x + threadIdx.x;
    if (i < KPROT) { g_S[i] = 0.f; g_r[i] = 1.f; g_maxd[i] = 0; }
    if (i < MROWS) { g_c[i] = 1.f; }
    if (i < 4)     { g_acc[i] = 0.f; }
}

// ---------------- normalize + int8 quantize: warp-per-row -------------------------
// codes = rint(x * 127 / absmax(x))   (direction only -> shared raw/normalized W)
// dequant scales: normalized = absmax*inv/127 ; raw = absmax/127
__global__ void __launch_bounds__(256)
quant_all_kernel(const float* __restrict__ t, const float* __restrict__ s,
                 const float* __restrict__ w) {
    int wid = threadIdx.x >> 5, lane = threadIdx.x & 31;
    int row = blockIdx.x * 8 + wid;
    int seg = blockIdx.y;
    const float* in = (seg == 0) ? t : (seg == 1) ? s : w;
    int8_t* codes = (seg == 0) ? g_ti8 : (seg == 1) ? g_si8 : g_wi8;
    const float4* x = (const float4*)(in + (size_t)row * DDIM);
    float4 v[6];
    float ss = 0.f, am = 0.f;
#pragma unroll
    for (int i = 0; i < 6; i++) {
        v[i] = x[i * 32 + lane];
        ss += v[i].x * v[i].x + v[i].y * v[i].y + v[i].z * v[i].z + v[i].w * v[i].w;
        am = fmaxf(am, fmaxf(fmaxf(fabsf(v[i].x), fabsf(v[i].y)),
                             fmaxf(fabsf(v[i].z), fabsf(v[i].w))));
    }
#pragma unroll
    for (int o = 16; o > 0; o >>= 1) {
        ss += __shfl_xor_sync(0xffffffffu, ss, o);
        am = fmaxf(am, __shfl_xor_sync(0xffffffffu, am, o));
    }
    float inv = 1.f / fmaxf(sqrtf(ss), 1e-12f);
    am = fmaxf(am, 1e-20f);
    float qs = 127.f / am;
    uchar4* oc = (uchar4*)(codes + (size_t)row * DDIM);
#pragma unroll
    for (int i = 0; i < 6; i++) {
        uchar4 c;
        c.x = (unsigned char)(signed char)__float2int_rn(v[i].x * qs);
        c.y = (unsigned char)(signed char)__float2int_rn(v[i].y * qs);
        c.z = (unsigned char)(signed char)__float2int_rn(v[i].z * qs);
        c.w = (unsigned char)(signed char)__float2int_rn(v[i].w * qs);
        oc[i * 32 + lane] = c;
    }
    if (lane == 0) {
        float scn = am * inv * (1.f / 127.f);
        if (seg == 0)      g_scT[row] = scn;
        else if (seg == 1) g_scS[row] = scn;
        else { g_scWr[row] = am * (1.f / 127.f); g_scWn[row] = scn; }
    }
}

// ---------------- warp-MMA int8 GEMM, all 3 products in ONE launch ----------------
// blockIdx.z: 0: t x W^T (raw scales) -> g_Lt + g_Et + fused S1 colsum
//             1: s x W^T (raw scales) -> g_Ls
//             2: Wn x Wn^T (normalized scales, symmetric lower triangle) -> g_maxd

#define ROWB 80                 // 64 data bytes per row + 16 pad
#define TILEB (128 * ROWB)      // 10240 bytes per tile buffer

__device__ __forceinline__ uint32_t smem_u32(const void* p) {
    uint32_t a;
    asm("{ .reg .u64 t; cvta.to.shared.u64 t, %1; cvt.u32.u64 %0, t; }" : "=r"(a) : "l"(p));
    return a;
}
__device__ __forceinline__ void ldsm_x4(uint32_t& r0, uint32_t& r1, uint32_t& r2, uint32_t& r3,
                                        uint32_t addr) {
    asm volatile("ldmatrix.sync.aligned.m8n8.x4.shared.b16 {%0,%1,%2,%3}, [%4];"
                 : "=r"(r0), "=r"(r1), "=r"(r2), "=r"(r3) : "r"(addr));
}
__device__ __forceinline__ void mma_s8(int* c, uint32_t a0, uint32_t a1, uint32_t a2,
                                       uint32_t a3, uint32_t b0, uint32_t b1) {
    asm volatile("mma.sync.aligned.m16n8k32.row.col.s32.s8.s8.s32 "
                 "{%0,%1,%2,%3}, {%4,%5,%6,%7}, {%8,%9}, {%0,%1,%2,%3};"
                 : "+r"(c[0]), "+r"(c[1]), "+r"(c[2]), "+r"(c[3])
                 : "r"(a0), "r"(a1), "r"(a2), "r"(a3), "r"(b0), "r"(b1));
}
__device__ __forceinline__ void cpasync16(uint32_t dst, const void* src) {
    asm volatile("cp.async.cg.shared.global [%0], [%1], 16;" :: "r"(dst), "l"(src) : "memory");
}

__global__ void __launch_bounds__(256, 2)
gemm_all_kernel() {
    const int mode = blockIdx.z;
    if (mode == 2 && blockIdx.x > blockIdx.y) return;  // symmetric: lower triangle only

    __shared__ __align__(16) uint8_t smem[4 * TILEB];
    const int8_t* A = (mode == 0) ? g_ti8 : (mode == 1) ? g_si8 : g_wi8;
    const int8_t* B = g_wi8;                        // shared direction codes
    const float* saP = (mode == 0) ? g_scT : (mode == 1) ? g_scS : g_scWn;
    const float* sbP = (mode == 2) ? g_scWn : g_scWr;
    __half* C = (mode == 0) ? g_Lt : g_Ls;

    int tid = threadIdx.x, wid = tid >> 5, lane = tid & 31;
    int m0 = blockIdx.y * 128, n0 = blockIdx.x * 128;
    int wm = (wid >> 2) * 64, wn = (wid & 3) * 32;

    uint32_t sb = smem_u32(smem);
    uint32_t sA[2] = {sb, sb + TILEB};
    uint32_t sB[2] = {sb + 2 * TILEB, sb + 3 * TILEB};

    int acc[4][4][4];
#pragma unroll
    for (int i = 0; i < 4; i++)
#pragma unroll
        for (int j = 0; j < 4; j++)
#pragma unroll
            for (int q = 0; q < 4; q++) acc[i][j][q] = 0;

    const int8_t* gA = A + (size_t)m0 * DDIM;
    const int8_t* gB = B + (size_t)n0 * DDIM;
    int r0c = tid >> 1, q0c = (tid & 1) << 1;       // 512 chunks: c=2*tid.. hmm use explicit:
    // 512 chunks of 16B per matrix (128 rows x 4); thread handles chunks tid, tid+256
    int rA0 = tid >> 2, qA0 = tid & 3;
    int rA1 = (tid + 256) >> 2, qA1 = tid & 3;
    (void)r0c; (void)q0c;

    // ldmatrix lane addressing: row = base + (lane&15), 16B k-offset = (lane>>4)*16
    int lrow = lane & 15;
    int lkoff = (lane >> 4) * 16;

#define LOAD_TILE(buf, kt) do {                                               \
    int koff = (kt) * 64;                                                     \
    cpasync16(sA[buf] + rA0 * ROWB + qA0 * 16, gA + (size_t)rA0 * DDIM + koff + qA0 * 16); \
    cpasync16(sB[buf] + rA0 * ROWB + qA0 * 16, gB + (size_t)rA0 * DDIM + koff + qA0 * 16); \
    cpasync16(sA[buf] + rA1 * ROWB + qA1 * 16, gA + (size_t)rA1 * DDIM + koff + qA1 * 16); \
    cpasync16(sB[buf] + rA1 * ROWB + qA1 * 16, gB + (size_t)rA1 * DDIM + koff + qA1 * 16); \
    asm volatile("cp.async.commit_group;" ::: "memory");                      \
} while (0)

    LOAD_TILE(0, 0);

    const int NKT = DDIM / 64;   // 12 tiles of 64 int8
#pragma unroll 1
    for (int kt = 0; kt < NKT; kt++) {
        int buf = kt & 1;
        if (kt + 1 < NKT) {
            LOAD_TILE(buf ^ 1, kt + 1);
            asm volatile("cp.async.wait_group 1;" ::: "memory");
        } else {
            asm volatile("cp.async.wait_group 0;" ::: "memory");
        }
        __syncthreads();
#pragma unroll
        for (int ks = 0; ks < 2; ks++) {
            uint32_t a[4][4], b[2][4];
#pragma unroll
            for (int mi = 0; mi < 4; mi++)
                ldsm_x4(a[mi][0], a[mi][1], a[mi][2], a[mi][3],
                        sA[buf] + (uint32_t)((wm + mi * 16 + lrow) * ROWB + ks * 32 + lkoff));
#pragma unroll
            for (int np = 0; np < 2; np++)
                ldsm_x4(b[np][0], b[np][1], b[np][2], b[np][3],
                        sB[buf] + (uint32_t)((wn + np * 16 + lrow) * ROWB + ks * 32 + lkoff));
#pragma unroll
            for (int mi = 0; mi < 4; mi++)
#pragma unroll
                for (int ni = 0; ni < 4; ni++) {
                    int np = ni >> 1, sel = ni & 1;
                    mma_s8(acc[mi][ni], a[mi][0], a[mi][1], a[mi][2], a[mi][3],
                           b[np][sel], b[np][sel + 2]);
                }
        }
        __syncthreads();
    }
#undef LOAD_TILE

    int tr = lane >> 2, tc = (lane & 3) * 2;

    // dequant scales for this thread's rows/cols
    float sa0[4], sa1[4], sb0[4], sb1[4];
#pragma unroll
    for (int mi = 0; mi < 4; mi++) {
        int gr = m0 + wm + mi * 16 + tr;
        sa0[mi] = saP[gr];
        sa1[mi] = saP[gr + 8];
    }
#pragma unroll
    for (int ni = 0; ni < 4; ni++) {
        int gc = n0 + wn + ni * 8 + tc;
        sb0[ni] = sbP[gc];
        sb1[ni] = sbP[gc + 1];
    }

    if (mode == 0) {
        float es[4][4][4];
#pragma unroll
        for (int mi = 0; mi < 4; mi++) {
            int gr0 = m0 + wm + mi * 16 + tr;
#pragma unroll
            for (int ni = 0; ni < 4; ni++) {
                int gc = n0 + wn + ni * 8 + tc;
                float L0 = (float)acc[mi][ni][0] * sa0[mi] * sb0[ni];
                float L1 = (float)acc[mi][ni][1] * sa0[mi] * sb1[ni];
                float L2 = (float)acc[mi][ni][2] * sa1[mi] * sb0[ni];
                float L3 = (float)acc[mi][ni][3] * sa1[mi] * sb1[ni];
                float e0 = __expf(L0 * INV_TT - SHIFT);
                float e1 = __expf(L1 * INV_TT - SHIFT);
                float e2 = __expf(L2 * INV_TT - SHIFT);
                float e3 = __expf(L3 * INV_TT - SHIFT);
                *(__half2*)&C[(size_t)gr0 * KPROT + gc] = __floats2half2_rn(L0, L1);
                *(__half2*)&C[(size_t)(gr0 + 8) * KPROT + gc] = __floats2half2_rn(L2, L3);
                *(__half2*)&g_Et[(size_t)gr0 * KPROT + gc] = __floats2half2_rn(e0, e1);
                *(__half2*)&g_Et[(size_t)(gr0 + 8) * KPROT + gc] = __floats2half2_rn(e2, e3);
                es[mi][ni][0] = e0; es[mi][ni][1] = e1;
                es[mi][ni][2] = e2; es[mi][ni][3] = e3;
            }
        }
#pragma unroll
        for (int ni = 0; ni < 4; ni++) {
            float s0 = 0.f, s1 = 0.f;
#pragma unroll
            for (int mi = 0; mi < 4; mi++) {
                s0 += es[mi][ni][0] + es[mi][ni][2];
                s1 += es[mi][ni][1] + es[mi][ni][3];
            }
#pragma unroll
            for (int o = 4; o < 32; o <<= 1) {
                s0 += __shfl_down_sync(0xffffffffu, s0, o);
                s1 += __shfl_down_sync(0xffffffffu, s1, o);
            }
            if (lane < 4) {
                int gc = n0 + wn + ni * 8 + lane * 2;
                atomicAdd(&g_S[gc], s0);
                atomicAdd(&g_S[gc + 1], s1);
            }
        }
    } else if (mode == 1) {
#pragma unroll
        for (int mi = 0; mi < 4; mi++) {
            int gr0 = m0 + wm + mi * 16 + tr;
#pragma unroll
            for (int ni = 0; ni < 4; ni++) {
                int gc = n0 + wn + ni * 8 + tc;
                float L0 = (float)acc[mi][ni][0] * sa0[mi] * sb0[ni];
                float L1 = (float)acc[mi][ni][1] * sa0[mi] * sb1[ni];
                float L2 = (float)acc[mi][ni][2] * sa1[mi] * sb0[ni];
                float L3 = (float)acc[mi][ni][3] * sa1[mi] * sb1[ni];
                *(__half2*)&C[(size_t)gr0 * KPROT + gc] = __floats2half2_rn(L0, L1);
                *(__half2*)&C[(size_t)(gr0 + 8) * KPROT + gc] = __floats2half2_rn(L2, L3);
            }
        }
    } else {
        float cm[4][2];
#pragma unroll
        for (int ni = 0; ni < 4; ni++) { cm[ni][0] = -2.f; cm[ni][1] = -2.f; }
#pragma unroll
        for (int mi = 0; mi < 4; mi++) {
            int gr0 = m0 + wm + mi * 16 + tr;
            int gr1 = gr0 + 8;
            float mx0 = -2.f, mx1 = -2.f;
#pragma unroll
            for (int ni = 0; ni < 4; ni++) {
                int gc = n0 + wn + ni * 8 + tc;
                float L0 = (float)acc[mi][ni][0] * sa0[mi] * sb0[ni];
                float L1 = (float)acc[mi][ni][1] * sa0[mi] * sb1[ni];
                float L2 = (float)acc[mi][ni][2] * sa1[mi] * sb0[ni];
                float L3 = (float)acc[mi][ni][3] * sa1[mi] * sb1[ni];
                float v0 = (gc == gr0) ? -2.f : L0;
                float v1 = (gc + 1 == gr0) ? -2.f : L1;
                float v2 = (gc == gr1) ? -2.f : L2;
                float v3 = (gc + 1 == gr1) ? -2.f : L3;
                mx0 = fmaxf(mx0, fmaxf(v0, v1));
                mx1 = fmaxf(mx1, fmaxf(v2, v3));
                cm[ni][0] = fmaxf(cm[ni][0], fmaxf(v0, v2));
                cm[ni][1] = fmaxf(cm[ni][1], fmaxf(v1, v3));
            }
#pragma unroll
            for (int o = 1; o < 4; o <<= 1) {
                mx0 = fmaxf(mx0, __shfl_xor_sync(0xffffffffu, mx0, o));
                mx1 = fmaxf(mx1, __shfl_xor_sync(0xffffffffu, mx1, o));
            }
            if ((lane & 3) == 0) {
                atomicMax(&g_maxd[gr0], __float_as_int(mx0 + 2.0f));
                atomicMax(&g_maxd[gr1], __float_as_int(mx1 + 2.0f));
            }
        }
        // mirrored (upper-triangle) coverage via column maxes
#pragma unroll
        for (int ni = 0; ni < 4; ni++) {
            float c0 = cm[ni][0], c1 = cm[ni][1];
#pragma unroll
            for (int o = 4; o < 32; o <<= 1) {
                c0 = fmaxf(c0, __shfl_xor_sync(0xffffffffu, c0, o));
                c1 = fmaxf(c1, __shfl_xor_sync(0xffffffffu, c1, o));
            }
            if (lane < 4) {
                int gc = n0 + wn + ni * 8 + lane * 2;
                atomicMax(&g_maxd[gc], __float_as_int(c0 + 2.0f));
                atomicMax(&g_maxd[gc + 1], __float_as_int(c1 + 2.0f));
            }
        }
    }
}

// ---------------- helpers --------------------------------------------------------
__device__ __forceinline__ void h8_to_f(const uint4& u, float f[8]) {
    __half2 a = *(const __half2*)&u.x, b = *(const __half2*)&u.y;
    __half2 c = *(const __half2*)&u.z, d = *(const __half2*)&u.w;
    float2 fa = __half22float2(a), fb = __half22float2(b);
    float2 fc = __half22float2(c), fd = __half22float2(d);
    f[0] = fa.x; f[1] = fa.y; f[2] = fb.x; f[3] = fb.y;
    f[4] = fc.x; f[5] = fc.y; f[6] = fd.x; f[7] = fd.y;
}

// ---------------- Sinkhorn passes (exp-free: use stored E) -------------------------
__global__ void r_update_kernel() {
    int k = blockIdx.x * blockDim.x + threadIdx.x;
    if (k < KPROT) {
        float r = g_r[k], s = g_S[k];
        g_r[k] = r / (r * s + SK_EPS);
        g_S[k] = 0.f;
    }
}

__global__ void pass_T_kernel() {
    int m = blockIdx.x;
    const uint4* row = (const uint4*)(g_Et + (size_t)m * KPROT);
    float t = 0.f;
    for (int i = threadIdx.x; i < KPROT / 8; i += blockDim.x) {
        uint4 u = row[i];
        float ev[8];
        h8_to_f(u, ev);
        float4 r0 = *(const float4*)(g_r + i * 8);
        float4 r1 = *(const float4*)(g_r + i * 8 + 4);
        t += ev[0] * r0.x + ev[1] * r0.y + ev[2] * r0.z + ev[3] * r0.w
           + ev[4] * r1.x + ev[5] * r1.y + ev[6] * r1.z + ev[7] * r1.w;
    }
    t = blockSum(t);
    if (threadIdx.x == 0) {
        float co = g_c[m];
        g_c[m] = co / (co * t + SK_EPS);
    }
}

__global__ void pass_S_kernel() {
    int k = blockIdx.x * blockDim.x + threadIdx.x;
    int m0 = blockIdx.y * 64;
    __shared__ float cs[64];
    if (threadIdx.x < 64) cs[threadIdx.x] = g_c[m0 + threadIdx.x];
    __syncthreads();
    float s = 0.f;
#pragma unroll 8
    for (int r = 0; r < 64; r++) {
        float ev = __half2float(g_Et[(size_t)(m0 + r) * KPROT + k]);
        s = fmaf(ev, cs[r], s);
    }
    atomicAdd(&g_S[k], s);
}

// ---------------- fused loss pass ----------------------------------------------
__global__ void loss_kernel() {
    int m = blockIdx.x;
    const uint4* etr = (const uint4*)(g_Et + (size_t)m * KPROT);
    const uint4* ltr = (const uint4*)(g_Lt + (size_t)m * KPROT);
    const uint4* lsr = (const uint4*)(g_Ls + (size_t)m * KPROT);
    float A = 0.f, Bv = 0.f, Dv = 0.f, Cv = 0.f, F = 0.f;
    for (int i = threadIdx.x; i < KPROT / 8; i += blockDim.x) {
        uint4 ue = etr[i], ut = ltr[i], us = lsr[i];
        float ev[8], lt[8], ls[8];
        h8_to_f(ue, ev);
        h8_to_f(ut, lt);
        h8_to_f(us, ls);
        float4 r0 = *(const float4*)(g_r + i * 8);
        float4 r1 = *(const float4*)(g_r + i * 8 + 4);
        float rr[8] = {r0.x, r0.y, r0.z, r0.w, r1.x, r1.y, r1.z, r1.w};
#pragma unroll
        for (int j = 0; j < 8; j++) {
            float e  = ev[j];
            float er = e * rr[j];
            A  += er;
            Bv = fmaf(er, lt[j], Bv);
            Dv += e;
            Cv = fmaf(er, ls[j], Cv);
            F  += __expf(ls[j] * INV_ST);
        }
    }
    A  = blockSum(A);
    Bv = blockSum(Bv);
    Dv = blockSum(Dv);
    Cv = blockSum(Cv);
    F  = blockSum(F);
    if (threadIdx.x == 0) {
        float co = g_c[m];
        float c3 = co / (co * A + SK_EPS);
        float lse_t = logf(Dv) + SHIFT;
        float lse_s = logf(F);
        float tpt = c3 * (A * lse_t - Bv * INV_TT);
        float spt = c3 * (A * lse_s - Cv * INV_ST);
        atomicAdd(&g_acc[0], tpt);
        float mm = g_msk[m];
        atomicAdd(&g_acc[1], mm * spt);
        atomicAdd(&g_acc[2], mm);
    }
}

__global__ void koleo_kernel() {
    int k = blockIdx.x * blockDim.x + threadIdx.x;
    float term = 0.f;
    if (k < KPROT) {
        float g = __int_as_float(g_maxd[k]) - 2.0f;
        float d = sqrtf(fmaxf(2.f - 2.f * g, 0.f));
        term = logf(d + 1e-8f);
    }
    term = blockSum(term);
    if (threadIdx.x == 0) atomicAdd(&g_acc[3], term);
}

__global__ void finalize_kernel(float* __restrict__ out) {
    if (threadIdx.x == 0) {
        out[0] = g_acc[1] / fmaxf(g_acc[2], 1.f);
        out[1] = g_acc[0] * (1.f / (float)MROWS);
        out[2] = -g_acc[3] * (1.f / (float)KPROT);
    }
}

// ---------------- launch (single stream) ---------------------------------------------
extern "C" void kernel_launch(void* const* d_in, const int* in_sizes, int n_in,
                              void* d_out, int out_size) {
    int midx = -1;
    for (int i = 0; i < n_in; i++)
        if (in_sizes[i] == MROWS) { midx = i; break; }
    if (midx < 0) midx = 2;
    int others[3], no = 0;
    for (int i = 0; i < n_in && no < 3; i++)
        if (i != midx) others[no++] = i;

    const float* teacher = (const float*)d_in[others[0]];
    const float* student = (const float*)d_in[others[1]];
    const float* W       = (const float*)d_in[others[2]];
    const void*  mask    = d_in[midx];

    detect_mask_kernel<<<1, 256>>>((const unsigned char*)mask);
    build_mask_kernel<<<32, 256>>>(mask);
    init_kernel<<<32, 256>>>();

    quant_all_kernel<<<dim3(MROWS / 8, 3), 256>>>(teacher, student, W);

    // all three GEMMs in one int8 launch: z=0 teacher(+E+S1), z=1 student, z=2 koleo
    gemm_all_kernel<<<dim3(KPROT / 128, MROWS / 128, 3), 256>>>();

    // Sinkhorn: S1 fused -> r1 ; T -> c1 ; S2 -> r2 ; T -> c2 ; S3 -> r3 ; T3 fused in loss
    r_update_kernel<<<KPROT / 256, 256>>>();
    pass_T_kernel<<<MROWS, 256>>>();
    pass_S_kernel<<<dim3(KPROT / 256, MROWS / 64), 256>>>();
    r_update_kernel<<<KPROT / 256, 256>>>();
    pass_T_kernel<<<MROWS, 256>>>();
    pass_S_kernel<<<dim3(KPROT / 256, MROWS / 64), 256>>>();
    r_update_kernel<<<KPROT / 256, 256>>>();

    loss_kernel<<<MROWS, 256>>>();
    koleo_kernel<<<KPROT / 256, 256>>>();
    finalize_kernel<<<1, 32>>>((float*)d_out);
    (void)out_size;
}

// round 7
// speedup vs baseline: 1.8790x; 1.8790x over previous
#include <cuda_runtime.h>
#include <cuda_fp16.h>
#include <cstdint>

#define MROWS 8192   // B*N tokens
#define KPROT 8192   // prototypes
#define DDIM  768
#define TTEMP 0.07f
#define INV_TT (1.0f/0.07f)
#define INV_ST 10.0f
#define SK_EPS 1e-8f
#define SHIFT  9.0f

// ---------------- scratch (static device globals; no allocation) -------------
static __device__ __align__(16) __half g_Ls[(size_t)MROWS * KPROT];  // student logits
static __device__ __align__(16) __half g_Et[(size_t)MROWS * KPROT]; // exp(Lt/tt - shift)
static __device__ __align__(16) __half g_th[MROWS * DDIM];
static __device__ __align__(16) __half g_sh[MROWS * DDIM];
static __device__ __align__(16) __half g_whr[KPROT * DDIM];
static __device__ __align__(16) __half g_whn[KPROT * DDIM];
static __device__ float  g_S[KPROT];
static __device__ float  g_r[KPROT];
static __device__ float  g_c[MROWS];
static __device__ float  g_msk[MROWS];
static __device__ int    g_maxd[KPROT];
static __device__ float  g_acc[4];
static __device__ int    g_maskmode;

// ---------------- reductions ---------------------------------------------------
__device__ __forceinline__ float warpSum(float v) {
#pragma unroll
    for (int o = 16; o > 0; o >>= 1) v += __shfl_down_sync(0xffffffffu, v, o);
    return v;
}
__device__ float blockSum(float v) {
    __shared__ float sb[32];
    int lane = threadIdx.x & 31, w = threadIdx.x >> 5;
    v = warpSum(v);
    __syncthreads();
    if (lane == 0) sb[w] = v;
    __syncthreads();
    int nw = (blockDim.x + 31) >> 5;
    v = (threadIdx.x < nw) ? sb[threadIdx.x] : 0.f;
    if (w == 0) v = warpSum(v);
    return v;
}

// ---------------- mask handling -------------------------------------------------
__global__ void detect_mask_kernel(const unsigned char* __restrict__ p) {
    __shared__ int c0, c1, c23;
    if (threadIdx.x == 0) { c0 = 0; c1 = 0; c23 = 0; }
    __syncthreads();
    int l0 = 0, l1 = 0, l23 = 0;
    for (int i = threadIdx.x; i < MROWS; i += blockDim.x) {
        unsigned char b = p[i];
        if (b) { int r = i & 3; if (r == 0) l0++; else if (r == 1) l1++; else l23++; }
    }
    atomicAdd(&c0, l0); atomicAdd(&c1, l1); atomicAdd(&c23, l23);
    __syncthreads();
    if (threadIdx.x == 0) {
        int mode;
        if (c1 == 0 && c23 == 0) mode = (c0 > 0) ? 1 : 0;
        else if (c1 == 0)        mode = 2;
        else                     mode = 0;
        g_maskmode = mode;
    }
}
__global__ void build_mask_kernel(const void* __restrict__ p) {
    int m = blockIdx.x * blockDim.x + threadIdx.x;
    if (m >= MROWS) return;
    int mode = g_maskmode;
    float v;
    if (mode == 1)      v = (((const int*)p)[m] != 0) ? 1.f : 0.f;
    else if (mode == 2) v = (((const float*)p)[m] != 0.f) ? 1.f : 0.f;
    else                v = (((const unsigned char*)p)[m] != 0) ? 1.f : 0.f;
    g_msk[m] = v;
}

__global__ void init_kernel() {
    int i = blockIdx.x * blockDim.x + threadIdx.x;
    if (i < KPROT) { g_S[i] = 0.f; g_r[i] = 1.f; g_maxd[i] = 0; }
    if (i < MROWS) { g_c[i] = 1.f; }
    if (i < 4)     { g_acc[i] = 0.f; }
}

// ---------------- normalize: warp-per-row, 3 segments in one launch --------------
__global__ void __launch_bounds__(256)
norm_all_kernel(const float* __restrict__ t, const float* __restrict__ s,
                const float* __restrict__ w) {
    int wid = threadIdx.x >> 5, lane = threadIdx.x & 31;
    int row = blockIdx.x * 8 + wid;
    int seg = blockIdx.y;
    const float* in = (seg == 0) ? t : (seg == 1) ? s : w;
    __half* outN = (seg == 0) ? g_th : (seg == 1) ? g_sh : g_whn;
    const float4* x = (const float4*)(in + (size_t)row * DDIM);
    float4 v[6];
    float ss = 0.f;
#pragma unroll
    for (int i = 0; i < 6; i++) {
        v[i] = x[i * 32 + lane];
        ss += v[i].x * v[i].x + v[i].y * v[i].y + v[i].z * v[i].z + v[i].w * v[i].w;
    }
#pragma unroll
    for (int o = 16; o > 0; o >>= 1) ss += __shfl_xor_sync(0xffffffffu, ss, o);
    float inv = 1.f / fmaxf(sqrtf(ss), 1e-12f);
    uint2* oN = (uint2*)(outN + (size_t)row * DDIM);
#pragma unroll
    for (int i = 0; i < 6; i++) {
        __half2 h0 = __floats2half2_rn(v[i].x * inv, v[i].y * inv);
        __half2 h1 = __floats2half2_rn(v[i].z * inv, v[i].w * inv);
        uint2 u; u.x = *(uint32_t*)&h0; u.y = *(uint32_t*)&h1;
        oN[i * 32 + lane] = u;
    }
    if (seg == 2) {
        uint2* oR = (uint2*)(g_whr + (size_t)row * DDIM);
#pragma unroll
        for (int i = 0; i < 6; i++) {
            __half2 h0 = __floats2half2_rn(v[i].x, v[i].y);
            __half2 h1 = __floats2half2_rn(v[i].z, v[i].w);
            uint2 u; u.x = *(uint32_t*)&h0; u.y = *(uint32_t*)&h1;
            oR[i * 32 + lane] = u;
        }
    }
}

// ---------------- warp-MMA fp16 GEMM, all 3 products in ONE launch ----------------
// blockIdx.z: 0: g_th x g_whr^T -> g_Et (+ fused S1 colsum); no logits stored
//             1: g_sh x g_whr^T -> g_Ls
//             2: g_whn x g_whn^T (symmetric, lower triangle) -> row/col max g_maxd

#define ROWB 80
#define TILEB (128 * ROWB)

__device__ __forceinline__ uint32_t smem_u32(const void* p) {
    uint32_t a;
    asm("{ .reg .u64 t; cvta.to.shared.u64 t, %1; cvt.u32.u64 %0, t; }" : "=r"(a) : "l"(p));
    return a;
}
__device__ __forceinline__ void ldsm_x4(uint32_t& r0, uint32_t& r1, uint32_t& r2, uint32_t& r3,
                                        uint32_t addr) {
    asm volatile("ldmatrix.sync.aligned.m8n8.x4.shared.b16 {%0,%1,%2,%3}, [%4];"
                 : "=r"(r0), "=r"(r1), "=r"(r2), "=r"(r3) : "r"(addr));
}
__device__ __forceinline__ void mma16816(float* c, uint32_t a0, uint32_t a1, uint32_t a2,
                                         uint32_t a3, uint32_t b0, uint32_t b1) {
    asm volatile("mma.sync.aligned.m16n8k16.row.col.f32.f16.f16.f32 "
                 "{%0,%1,%2,%3}, {%4,%5,%6,%7}, {%8,%9}, {%0,%1,%2,%3};"
                 : "+f"(c[0]), "+f"(c[1]), "+f"(c[2]), "+f"(c[3])
                 : "r"(a0), "r"(a1), "r"(a2), "r"(a3), "r"(b0), "r"(b1));
}
__device__ __forceinline__ void cpasync16(uint32_t dst, const void* src) {
    asm volatile("cp.async.cg.shared.global [%0], [%1], 16;" :: "r"(dst), "l"(src) : "memory");
}

__global__ void __launch_bounds__(256, 2)
gemm_all_kernel() {
    const int mode = blockIdx.z;
    if (mode == 2 && blockIdx.x > blockIdx.y) return;  // symmetric: lower triangle only

    __shared__ __align__(16) uint8_t smem[4 * TILEB];
    const __half* A = (mode == 0) ? g_th : (mode == 1) ? g_sh : g_whn;
    const __half* B = (mode == 2) ? g_whn : g_whr;

    int tid = threadIdx.x, wid = tid >> 5, lane = tid & 31;
    int m0 = blockIdx.y * 128, n0 = blockIdx.x * 128;
    int wm = (wid >> 2) * 64, wn = (wid & 3) * 32;

    uint32_t sb = smem_u32(smem);
    uint32_t sA[2] = {sb, sb + TILEB};
    uint32_t sB[2] = {sb + 2 * TILEB, sb + 3 * TILEB};

    float acc[4][4][4];
#pragma unroll
    for (int i = 0; i < 4; i++)
#pragma unroll
        for (int j = 0; j < 4; j++)
#pragma unroll
            for (int q = 0; q < 4; q++) acc[i][j][q] = 0.f;

    const __half* gA = A + (size_t)m0 * DDIM;
    const __half* gB = B + (size_t)n0 * DDIM;
    int r0c = tid >> 2, q0c = tid & 3;
    int r1c = (tid + 256) >> 2, q1c = tid & 3;

    int aRow = wm + (lane & 15);
    int aColB = (lane >> 4) * 16;
    int bRow = wn + (lane & 7) + ((lane >> 4) << 3);
    int bColB = ((lane >> 3) & 1) * 16;

#define LOAD_TILE(buf, kt) do {                                               \
    int koff = (kt) * 32;                                                     \
    cpasync16(sA[buf] + r0c * ROWB + q0c * 16, gA + (size_t)r0c * DDIM + koff + q0c * 8); \
    cpasync16(sB[buf] + r0c * ROWB + q0c * 16, gB + (size_t)r0c * DDIM + koff + q0c * 8); \
    cpasync16(sA[buf] + r1c * ROWB + q1c * 16, gA + (size_t)r1c * DDIM + koff + q1c * 8); \
    cpasync16(sB[buf] + r1c * ROWB + q1c * 16, gB + (size_t)r1c * DDIM + koff + q1c * 8); \
    asm volatile("cp.async.commit_group;" ::: "memory");                      \
} while (0)

    LOAD_TILE(0, 0);

    const int NKT = DDIM / 32;
#pragma unroll 1
    for (int kt = 0; kt < NKT; kt++) {
        int buf = kt & 1;
        if (kt + 1 < NKT) {
            LOAD_TILE(buf ^ 1, kt + 1);
            asm volatile("cp.async.wait_group 1;" ::: "memory");
        } else {
            asm volatile("cp.async.wait_group 0;" ::: "memory");
        }
        __syncthreads();
#pragma unroll
        for (int ks = 0; ks < 2; ks++) {
            uint32_t a[4][4], b[2][4];
#pragma unroll
            for (int mi = 0; mi < 4; mi++)
                ldsm_x4(a[mi][0], a[mi][1], a[mi][2], a[mi][3],
                        sA[buf] + (uint32_t)((aRow + mi * 16) * ROWB + ks * 32 + aColB));
#pragma unroll
            for (int np = 0; np < 2; np++)
                ldsm_x4(b[np][0], b[np][1], b[np][2], b[np][3],
                        sB[buf] + (uint32_t)((bRow + np * 16) * ROWB + ks * 32 + bColB));
#pragma unroll
            for (int mi = 0; mi < 4; mi++)
#pragma unroll
                for (int ni = 0; ni < 4; ni++) {
                    int np = ni >> 1, sel = (ni & 1) * 2;
                    mma16816(acc[mi][ni], a[mi][0], a[mi][1], a[mi][2], a[mi][3],
                             b[np][sel], b[np][sel + 1]);
                }
        }
        __syncthreads();
    }
#undef LOAD_TILE

    int tr = lane >> 2, tc = (lane & 3) * 2;

    if (mode == 0) {
        // store only E = exp(L/tt - shift); fused colsum S1
#pragma unroll
        for (int mi = 0; mi < 4; mi++) {
            int gr0 = m0 + wm + mi * 16 + tr;
#pragma unroll
            for (int ni = 0; ni < 4; ni++) {
                int gc = n0 + wn + ni * 8 + tc;
                float e0 = __expf(acc[mi][ni][0] * INV_TT - SHIFT);
                float e1 = __expf(acc[mi][ni][1] * INV_TT - SHIFT);
                float e2 = __expf(acc[mi][ni][2] * INV_TT - SHIFT);
                float e3 = __expf(acc[mi][ni][3] * INV_TT - SHIFT);
                *(__half2*)&g_Et[(size_t)gr0 * KPROT + gc] = __floats2half2_rn(e0, e1);
                *(__half2*)&g_Et[(size_t)(gr0 + 8) * KPROT + gc] = __floats2half2_rn(e2, e3);
                acc[mi][ni][0] = e0; acc[mi][ni][1] = e1;
                acc[mi][ni][2] = e2; acc[mi][ni][3] = e3;
            }
        }
#pragma unroll
        for (int ni = 0; ni < 4; ni++) {
            float s0 = 0.f, s1 = 0.f;
#pragma unroll
            for (int mi = 0; mi < 4; mi++) {
                s0 += acc[mi][ni][0] + acc[mi][ni][2];
                s1 += acc[mi][ni][1] + acc[mi][ni][3];
            }
#pragma unroll
            for (int o = 4; o < 32; o <<= 1) {
                s0 += __shfl_down_sync(0xffffffffu, s0, o);
                s1 += __shfl_down_sync(0xffffffffu, s1, o);
            }
            if (lane < 4) {
                int gc = n0 + wn + ni * 8 + lane * 2;
                atomicAdd(&g_S[gc], s0);
                atomicAdd(&g_S[gc + 1], s1);
            }
        }
    } else if (mode == 1) {
#pragma unroll
        for (int mi = 0; mi < 4; mi++) {
            int gr0 = m0 + wm + mi * 16 + tr;
#pragma unroll
            for (int ni = 0; ni < 4; ni++) {
                int gc = n0 + wn + ni * 8 + tc;
                *(__half2*)&g_Ls[(size_t)gr0 * KPROT + gc] =
                    __floats2half2_rn(acc[mi][ni][0], acc[mi][ni][1]);
                *(__half2*)&g_Ls[(size_t)(gr0 + 8) * KPROT + gc] =
                    __floats2half2_rn(acc[mi][ni][2], acc[mi][ni][3]);
            }
        }
    } else {
        float cm[4][2];
#pragma unroll
        for (int ni = 0; ni < 4; ni++) { cm[ni][0] = -2.f; cm[ni][1] = -2.f; }
#pragma unroll
        for (int mi = 0; mi < 4; mi++) {
            int gr0 = m0 + wm + mi * 16 + tr;
            int gr1 = gr0 + 8;
            float mx0 = -2.f, mx1 = -2.f;
#pragma unroll
            for (int ni = 0; ni < 4; ni++) {
                int gc = n0 + wn + ni * 8 + tc;
                float v0 = (gc == gr0) ? -2.f : acc[mi][ni][0];
                float v1 = (gc + 1 == gr0) ? -2.f : acc[mi][ni][1];
                float v2 = (gc == gr1) ? -2.f : acc[mi][ni][2];
                float v3 = (gc + 1 == gr1) ? -2.f : acc[mi][ni][3];
                mx0 = fmaxf(mx0, fmaxf(v0, v1));
                mx1 = fmaxf(mx1, fmaxf(v2, v3));
                cm[ni][0] = fmaxf(cm[ni][0], fmaxf(v0, v2));
                cm[ni][1] = fmaxf(cm[ni][1], fmaxf(v1, v3));
            }
#pragma unroll
            for (int o = 1; o < 4; o <<= 1) {
                mx0 = fmaxf(mx0, __shfl_xor_sync(0xffffffffu, mx0, o));
                mx1 = fmaxf(mx1, __shfl_xor_sync(0xffffffffu, mx1, o));
            }
            if ((lane & 3) == 0) {
                atomicMax(&g_maxd[gr0], __float_as_int(mx0 + 2.0f));
                atomicMax(&g_maxd[gr1], __float_as_int(mx1 + 2.0f));
            }
        }
#pragma unroll
        for (int ni = 0; ni < 4; ni++) {
            float c0 = cm[ni][0], c1 = cm[ni][1];
#pragma unroll
            for (int o = 4; o < 32; o <<= 1) {
                c0 = fmaxf(c0, __shfl_xor_sync(0xffffffffu, c0, o));
                c1 = fmaxf(c1, __shfl_xor_sync(0xffffffffu, c1, o));
            }
            if (lane < 4) {
                int gc = n0 + wn + ni * 8 + lane * 2;
                atomicMax(&g_maxd[gc], __float_as_int(c0 + 2.0f));
                atomicMax(&g_maxd[gc + 1], __float_as_int(c1 + 2.0f));
            }
        }
    }
}

// ---------------- helpers --------------------------------------------------------
__device__ __forceinline__ void h8_to_f(const uint4& u, float f[8]) {
    __half2 a = *(const __half2*)&u.x, b = *(const __half2*)&u.y;
    __half2 c = *(const __half2*)&u.z, d = *(const __half2*)&u.w;
    float2 fa = __half22float2(a), fb = __half22float2(b);
    float2 fc = __half22float2(c), fd = __half22float2(d);
    f[0] = fa.x; f[1] = fa.y; f[2] = fb.x; f[3] = fb.y;
    f[4] = fc.x; f[5] = fc.y; f[6] = fd.x; f[7] = fd.y;
}

// ---------------- Sinkhorn passes (direction-alternating for L2 reuse) -------------
__global__ void r_update_kernel() {
    int k = blockIdx.x * blockDim.x + threadIdx.x;
    if (k < KPROT) {
        float r = g_r[k], s = g_S[k];
        g_r[k] = r / (r * s + SK_EPS);
        g_S[k] = 0.f;
    }
}

__global__ void pass_T_kernel(int rev) {
    int m = rev ? (MROWS - 1 - blockIdx.x) : blockIdx.x;
    const uint4* row = (const uint4*)(g_Et + (size_t)m * KPROT);
    float t = 0.f;
    for (int i = threadIdx.x; i < KPROT / 8; i += blockDim.x) {
        uint4 u = row[i];
        float ev[8];
        h8_to_f(u, ev);
        float4 r0 = *(const float4*)(g_r + i * 8);
        float4 r1 = *(const float4*)(g_r + i * 8 + 4);
        t += ev[0] * r0.x + ev[1] * r0.y + ev[2] * r0.z + ev[3] * r0.w
           + ev[4] * r1.x + ev[5] * r1.y + ev[6] * r1.z + ev[7] * r1.w;
    }
    t = blockSum(t);
    if (threadIdx.x == 0) {
        float co = g_c[m];
        g_c[m] = co / (co * t + SK_EPS);
    }
}

// S_k += sum over 64 rows of E*c ; vectorized: 8 cols per thread
__global__ void pass_S_kernel(int rev) {
    int yb = rev ? (gridDim.y - 1 - blockIdx.y) : blockIdx.y;
    int m0 = yb * 64;
    int k0 = (blockIdx.x * 256 + threadIdx.x) * 8;
    __shared__ float cs[64];
    if (threadIdx.x < 64) cs[threadIdx.x] = g_c[m0 + threadIdx.x];
    __syncthreads();
    float s[8] = {0.f, 0.f, 0.f, 0.f, 0.f, 0.f, 0.f, 0.f};
#pragma unroll 4
    for (int r = 0; r < 64; r++) {
        uint4 u = *(const uint4*)&g_Et[(size_t)(m0 + r) * KPROT + k0];
        float ev[8];
        h8_to_f(u, ev);
        float c = cs[r];
#pragma unroll
        for (int j = 0; j < 8; j++) s[j] = fmaf(ev[j], c, s[j]);
    }
#pragma unroll
    for (int j = 0; j < 8; j++) atomicAdd(&g_S[k0 + j], s[j]);
}

// ---------------- fused loss pass (ascending; Et hot in L2 from desc S3) -----------
__global__ void loss_kernel() {
    int m = blockIdx.x;
    const uint4* etr = (const uint4*)(g_Et + (size_t)m * KPROT);
    const uint4* lsr = (const uint4*)(g_Ls + (size_t)m * KPROT);
    float A = 0.f, Bq = 0.f, Dv = 0.f, Cv = 0.f, F = 0.f;
    for (int i = threadIdx.x; i < KPROT / 8; i += blockDim.x) {
        uint4 ue = etr[i], us = lsr[i];
        float ev[8], ls[8];
        h8_to_f(ue, ev);
        h8_to_f(us, ls);
        float4 r0 = *(const float4*)(g_r + i * 8);
        float4 r1 = *(const float4*)(g_r + i * 8 + 4);
        float rr[8] = {r0.x, r0.y, r0.z, r0.w, r1.x, r1.y, r1.z, r1.w};
#pragma unroll
        for (int j = 0; j < 8; j++) {
            float e  = ev[j];
            float er = e * rr[j];
            // lq = L/tt = ln(e) + SHIFT   (guard against fp16 underflow -> -inf)
            float lq = __logf(fmaxf(e, 6e-8f)) + SHIFT;
            A  += er;
            Bq = fmaf(er, lq, Bq);
            Dv += e;
            Cv = fmaf(er, ls[j], Cv);
            F  += __expf(ls[j] * INV_ST);
        }
    }
    A  = blockSum(A);
    Bq = blockSum(Bq);
    Dv = blockSum(Dv);
    Cv = blockSum(Cv);
    F  = blockSum(F);
    if (threadIdx.x == 0) {
        float co = g_c[m];
        float c3 = co / (co * A + SK_EPS);
        float lse_t = logf(Dv) + SHIFT;
        float lse_s = logf(F);
        float tpt = c3 * (A * lse_t - Bq);            // Bq already = sum er * L/tt
        float spt = c3 * (A * lse_s - Cv * INV_ST);
        atomicAdd(&g_acc[0], tpt);
        float mm = g_msk[m];
        atomicAdd(&g_acc[1], mm * spt);
        atomicAdd(&g_acc[2], mm);
    }
}

__global__ void koleo_kernel() {
    int k = blockIdx.x * blockDim.x + threadIdx.x;
    float term = 0.f;
    if (k < KPROT) {
        float g = __int_as_float(g_maxd[k]) - 2.0f;
        float d = sqrtf(fmaxf(2.f - 2.f * g, 0.f));
        term = logf(d + 1e-8f);
    }
    term = blockSum(term);
    if (threadIdx.x == 0) atomicAdd(&g_acc[3], term);
}

__global__ void finalize_kernel(float* __restrict__ out) {
    if (threadIdx.x == 0) {
        out[0] = g_acc[1] / fmaxf(g_acc[2], 1.f);
        out[1] = g_acc[0] * (1.f / (float)MROWS);
        out[2] = -g_acc[3] * (1.f / (float)KPROT);
    }
}

// ---------------- launch (single stream) ---------------------------------------------
extern "C" void kernel_launch(void* const* d_in, const int* in_sizes, int n_in,
                              void* d_out, int out_size) {
    int midx = -1;
    for (int i = 0; i < n_in; i++)
        if (in_sizes[i] == MROWS) { midx = i; break; }
    if (midx < 0) midx = 2;
    int others[3], no = 0;
    for (int i = 0; i < n_in && no < 3; i++)
        if (i != midx) others[no++] = i;

    const float* teacher = (const float*)d_in[others[0]];
    const float* student = (const float*)d_in[others[1]];
    const float* W       = (const float*)d_in[others[2]];
    const void*  mask    = d_in[midx];

    detect_mask_kernel<<<1, 256>>>((const unsigned char*)mask);
    build_mask_kernel<<<32, 256>>>(mask);
    init_kernel<<<32, 256>>>();

    norm_all_kernel<<<dim3(MROWS / 8, 3), 256>>>(teacher, student, W);

    // all three GEMMs in one launch: z=0 teacher(E+S1), z=1 student, z=2 koleo
    gemm_all_kernel<<<dim3(KPROT / 128, MROWS / 128, 3), 256>>>();

    // Sinkhorn with direction-alternating Et traversal (L2 ping-pong):
    // S1 fused in GEMM -> r1 ; T1 asc -> c1 ; S2 desc -> r2 ; T2 asc -> c2 ;
    // S3 desc -> r3 ; loss asc (T3 + c3 internal)
    r_update_kernel<<<KPROT / 256, 256>>>();
    pass_T_kernel<<<MROWS, 256>>>(0);
    pass_S_kernel<<<dim3(KPROT / 2048, MROWS / 64), 256>>>(1);
    r_update_kernel<<<KPROT / 256, 256>>>();
    pass_T_kernel<<<MROWS, 256>>>(0);
    pass_S_kernel<<<dim3(KPROT / 2048, MROWS / 64), 256>>>(1);
    r_update_kernel<<<KPROT / 256, 256>>>();

    loss_kernel<<<MROWS, 256>>>();
    koleo_kernel<<<KPROT / 256, 256>>>();
    finalize_kernel<<<1, 32>>>((float*)d_out);
    (void)out_size;
}